// round 12
// baseline (speedup 1.0000x reference)
#include <cuda_runtime.h>
#include <cuda_fp16.h>

// RadiosityPropagater — N=4096, 64 tail lights, 3 bounces.
//  bounce1: sparse gather over 64 light columns, fused combine -> g_B.
//  build:   full O(N^2) pass; bilinear-expanded geometry (d2/ti/tj from
//           precomputed per-point reductions), 2 packed f32x2 streams
//           (4 receivers/thread); gathers with B1 and stores F_T (fp16 x1024).
//  combine<0>: unrolled 64-split reduce -> g_B (= B2).
//  matvec:  measured-best plateau shape (512 blocks, 16-deep batches).
//  combine<1>: unrolled 64-split reduce + emis/brdf/relu -> d_out.
// Deterministic: no float atomics anywhere.

#define NMAX    4096
#define NLIGHTS 64
#define BLK     256
#define PBLK    128                // build block size
#define JT2     64
#define JS2     (NMAX / JT2)       // 64 j-splits in build
#define JT3     64
#define JS3     (NMAX / JT3)       // 64 j-splits in matvec
#define IT3     4
#define MBLK    128                // matvec block size
#define FSCALE  1024.0f
#define INV_S   (1.0f / 1024.0f)

typedef unsigned long long ull;

__device__ float  g_part[JS2 * NMAX * 3];       // partial gathers (both passes)
__device__ float  g_B[NMAX * 3];                // radiosity between bounces
__device__ __half g_F[(size_t)NMAX * NMAX];     // F_T[j][i] = 1024 * F[i][j]

__device__ __forceinline__ float frcp(float x) {
    float r; asm("rcp.approx.ftz.f32 %0, %1;" : "=f"(r) : "f"(x)); return r;
}
__device__ __forceinline__ ull pk(float lo, float hi) {
    ull r; asm("mov.b64 %0, {%1, %2};" : "=l"(r) : "f"(lo), "f"(hi)); return r;
}
__device__ __forceinline__ ull sp(float x) {
    ull r; asm("mov.b64 %0, {%1, %1};" : "=l"(r) : "f"(x)); return r;
}
__device__ __forceinline__ void upk(ull v, float& lo, float& hi) {
    asm("mov.b64 {%0, %1}, %2;" : "=f"(lo), "=f"(hi) : "l"(v));
}
__device__ __forceinline__ ull f2fma(ull a, ull b, ull c) {
    ull d; asm("fma.rn.f32x2 %0, %1, %2, %3;" : "=l"(d) : "l"(a), "l"(b), "l"(c)); return d;
}
__device__ __forceinline__ ull f2add(ull a, ull b) {
    ull d; asm("add.rn.f32x2 %0, %1, %2;" : "=l"(d) : "l"(a), "l"(b)); return d;
}

__device__ __forceinline__ float snf_scale(const float* s, const float* g,
                                           const float* nf, int j) {
    return s[3*j] * s[3*j+1] * g[j] * nf[j] * FSCALE;
}

// ---------------------------------------------------------------- bounce 1
__global__ void __launch_bounds__(BLK) bounce1_kernel(
        const float* __restrict__ means,  const float* __restrict__ geo,
        const float* __restrict__ scales, const float* __restrict__ normals,
        const float* __restrict__ nf,     const float* __restrict__ emis,
        const float* __restrict__ brdf,   int N) {
    __shared__ float4 sM[NLIGHTS];
    __shared__ float4 sS[NLIGHTS];
    __shared__ float  sC[NLIGHTS];
    int tid = threadIdx.x;
    if (tid < NLIGHTS) {
        int jg = N - NLIGHTS + tid;
        float a = snf_scale(scales, geo, nf, jg);
        sM[tid] = make_float4(means[3*jg], means[3*jg+1], means[3*jg+2],
                              emis[3*jg] * INV_S);
        sS[tid] = make_float4(normals[3*jg] * a, normals[3*jg+1] * a,
                              normals[3*jg+2] * a, emis[3*jg+1] * INV_S);
        sC[tid] = emis[3*jg+2] * INV_S;
    }
    __syncthreads();

    int i = blockIdx.x * BLK + tid;
    float rx = means[3*i],   ry = means[3*i+1],   rz = means[3*i+2];
    float nx = normals[3*i], ny = normals[3*i+1], nz = normals[3*i+2];
    float a0 = 0.f, a1 = 0.f, a2 = 0.f;
    #pragma unroll 8
    for (int j = 0; j < NLIGHTS; j++) {
        float4 M = sM[j]; float4 S = sS[j]; float c = sC[j];
        float dx = M.x - rx, dy = M.y - ry, dz = M.z - rz;
        float d2 = fmaf(dx, dx, fmaf(dy, dy, fmaf(dz, dz, 1e-8f)));
        float r  = frcp(d2);
        float rf = r * fminf(fmaxf(r, 1e-4f), 1.0f);
        float pi_ = fmaxf(fmaf(dx, nx,  fmaf(dy, ny,  dz * nz)),  0.f);
        float pj_ = fmaxf(-fmaf(dx, S.x, fmaf(dy, S.y, dz * S.z)), 0.f);
        float w = pi_ * (pj_ * rf);
        a0 = fmaf(w, M.w, a0); a1 = fmaf(w, S.w, a1); a2 = fmaf(w, c, a2);
    }
    bool light = (i >= N - NLIGHTS);
    float e0 = emis[3*i], e1 = emis[3*i+1], e2 = emis[3*i+2];
    g_B[3*i]   = light ? e0 : fmaf(brdf[3*i],   a0, e0);
    g_B[3*i+1] = light ? e1 : fmaf(brdf[3*i+1], a1, e1);
    g_B[3*i+2] = light ? e2 : fmaf(brdf[3*i+2], a2, e2);
}

// ------------------------------------------------------- bounce 2 + build F
// Bilinear geometry: per-emitter (m, u=|m|^2+eps, n'=a*n, e'=a*(m.n), B')
// staged pre-splatted; per-receiver (-m, -2m, n, -(m.n), |m|^2) packed.
//   d2 = (u + v) - 2 m_i.m_j     ti = m_j.n_i - c_i     g = e' - m_i.n'
//   w  = relu(ti) * relu(g) * min(r*r, r),  r = rcp(max(d2, 3e-5))
__global__ void __launch_bounds__(PBLK) build_kernel(
        const float* __restrict__ means,  const float* __restrict__ geo,
        const float* __restrict__ scales, const float* __restrict__ normals,
        const float* __restrict__ nf,     int N) {
    __shared__ ulonglong2 sMa[JT2];   // (mx, my) splatted
    __shared__ ulonglong2 sMb[JT2];   // (mz, u)  splatted
    __shared__ ulonglong2 sNa[JT2];   // (n'x, n'y) splatted
    __shared__ ulonglong2 sNb[JT2];   // (n'z, e')  splatted
    __shared__ ulonglong2 sBa[JT2];   // (B0', B1') splatted
    __shared__ ull        sBc[JT2];   // B2' splatted

    int tid = threadIdx.x;
    int j0  = blockIdx.y * JT2;
    if (tid < JT2) {
        int jg = j0 + tid;
        float a  = snf_scale(scales, geo, nf, jg);
        float mx = means[3*jg], my = means[3*jg+1], mz = means[3*jg+2];
        float nx = normals[3*jg], ny = normals[3*jg+1], nz = normals[3*jg+2];
        float e  = fmaf(mx, nx, fmaf(my, ny, mz * nz));
        float u  = fmaf(mx, mx, fmaf(my, my, fmaf(mz, mz, 1e-8f)));
        sMa[tid] = make_ulonglong2(sp(mx), sp(my));
        sMb[tid] = make_ulonglong2(sp(mz), sp(u));
        sNa[tid] = make_ulonglong2(sp(nx * a), sp(ny * a));
        sNb[tid] = make_ulonglong2(sp(nz * a), sp(e * a));
        sBa[tid] = make_ulonglong2(sp(g_B[3*jg] * INV_S), sp(g_B[3*jg+1] * INV_S));
        sBc[tid] = sp(g_B[3*jg+2] * INV_S);
    }
    __syncthreads();

    int i0 = (blockIdx.x * PBLK + tid) * 4;

    // receiver constants, stream A = (i0, i0+1), stream B = (i0+2, i0+3)
    float rm[12], rn[12];
    #pragma unroll
    for (int k = 0; k < 12; k++) { rm[k] = means[3*i0 + k]; rn[k] = normals[3*i0 + k]; }

    ull nmxA = pk(-rm[0], -rm[3]),  nmyA = pk(-rm[1], -rm[4]),  nmzA = pk(-rm[2], -rm[5]);
    ull m2xA = pk(-2.f*rm[0], -2.f*rm[3]), m2yA = pk(-2.f*rm[1], -2.f*rm[4]), m2zA = pk(-2.f*rm[2], -2.f*rm[5]);
    ull nxA  = pk(rn[0], rn[3]),    nyA  = pk(rn[1], rn[4]),    nzA  = pk(rn[2], rn[5]);
    ull ncA  = pk(-fmaf(rm[0],rn[0],fmaf(rm[1],rn[1],rm[2]*rn[2])),
                  -fmaf(rm[3],rn[3],fmaf(rm[4],rn[4],rm[5]*rn[5])));
    ull vA   = pk(fmaf(rm[0],rm[0],fmaf(rm[1],rm[1],rm[2]*rm[2])),
                  fmaf(rm[3],rm[3],fmaf(rm[4],rm[4],rm[5]*rm[5])));

    ull nmxB = pk(-rm[6], -rm[9]),  nmyB = pk(-rm[7], -rm[10]), nmzB = pk(-rm[8], -rm[11]);
    ull m2xB = pk(-2.f*rm[6], -2.f*rm[9]), m2yB = pk(-2.f*rm[7], -2.f*rm[10]), m2zB = pk(-2.f*rm[8], -2.f*rm[11]);
    ull nxB  = pk(rn[6], rn[9]),    nyB  = pk(rn[7], rn[10]),   nzB  = pk(rn[8], rn[11]);
    ull ncB  = pk(-fmaf(rm[6],rn[6],fmaf(rm[7],rn[7],rm[8]*rn[8])),
                  -fmaf(rm[9],rn[9],fmaf(rm[10],rn[10],rm[11]*rn[11])));
    ull vB   = pk(fmaf(rm[6],rm[6],fmaf(rm[7],rm[7],rm[8]*rm[8])),
                  fmaf(rm[9],rm[9],fmaf(rm[10],rm[10],rm[11]*rm[11])));

    ull a0A = 0ull, a1A = 0ull, a2A = 0ull;
    ull a0B = 0ull, a1B = 0ull, a2B = 0ull;
    __half* fpo = g_F + (size_t)j0 * N + i0;

    #pragma unroll 8
    for (int j = 0; j < JT2; j++) {
        ulonglong2 Ma = sMa[j], Mb = sMb[j], Na = sNa[j], Nb = sNb[j], Ba = sBa[j];
        ull Bc = sBc[j];

        ull d2A = f2fma(Ma.x, m2xA, f2fma(Ma.y, m2yA, f2fma(Mb.x, m2zA, f2add(Mb.y, vA))));
        ull tiA = f2fma(Ma.x, nxA,  f2fma(Ma.y, nyA,  f2fma(Mb.x, nzA,  ncA)));
        ull gA  = f2fma(Na.x, nmxA, f2fma(Na.y, nmyA, f2fma(Nb.x, nmzA, Nb.y)));
        ull d2B = f2fma(Ma.x, m2xB, f2fma(Ma.y, m2yB, f2fma(Mb.x, m2zB, f2add(Mb.y, vB))));
        ull tiB = f2fma(Ma.x, nxB,  f2fma(Ma.y, nyB,  f2fma(Mb.x, nzB,  ncB)));
        ull gB  = f2fma(Na.x, nmxB, f2fma(Na.y, nmyB, f2fma(Nb.x, nmzB, Nb.y)));

        float dA0, dA1, dB0, dB1, tA0, tA1, tB0, tB1, gA0, gA1, gB0, gB1;
        upk(d2A, dA0, dA1); upk(d2B, dB0, dB1);
        upk(tiA, tA0, tA1); upk(tiB, tB0, tB1);
        upk(gA,  gA0, gA1); upk(gB,  gB0, gB1);

        float rA0 = frcp(fmaxf(dA0, 3e-5f));
        float rA1 = frcp(fmaxf(dA1, 3e-5f));
        float rB0 = frcp(fmaxf(dB0, 3e-5f));
        float rB1 = frcp(fmaxf(dB1, 3e-5f));

        float wA0 = (fmaxf(tA0, 0.f) * fmaxf(gA0, 0.f)) * fminf(rA0 * rA0, rA0);
        float wA1 = (fmaxf(tA1, 0.f) * fmaxf(gA1, 0.f)) * fminf(rA1 * rA1, rA1);
        float wB0 = (fmaxf(tB0, 0.f) * fmaxf(gB0, 0.f)) * fminf(rB0 * rB0, rB0);
        float wB1 = (fmaxf(tB1, 0.f) * fmaxf(gB1, 0.f)) * fminf(rB1 * rB1, rB1);

        uint2 st;
        __half2 hA = __floats2half2_rn(wA0, wA1);
        __half2 hB = __floats2half2_rn(wB0, wB1);
        st.x = *(const unsigned*)&hA;
        st.y = *(const unsigned*)&hB;
        *(uint2*)fpo = st;                 // F_T[j0+j][i0..i0+3], 8B coalesced
        fpo += N;

        ull wAp = pk(wA0, wA1), wBp = pk(wB0, wB1);
        a0A = f2fma(wAp, Ba.x, a0A); a1A = f2fma(wAp, Ba.y, a1A); a2A = f2fma(wAp, Bc, a2A);
        a0B = f2fma(wBp, Ba.x, a0B); a1B = f2fma(wBp, Ba.y, a1B); a2B = f2fma(wBp, Bc, a2B);
    }

    float x00,x10,x01,x11,x02,x12, y00,y10,y01,y11,y02,y12;
    upk(a0A, x00, x10); upk(a1A, x01, x11); upk(a2A, x02, x12);
    upk(a0B, y00, y10); upk(a1B, y01, y11); upk(a2B, y02, y12);
    float* p = g_part + (size_t)blockIdx.y * NMAX * 3 + 3 * i0;
    ((float4*)p)[0] = make_float4(x00, x01, x02, x10);
    ((float4*)p)[1] = make_float4(x11, x12, y00, y01);
    ((float4*)p)[2] = make_float4(y02, y10, y11, y12);
}

// ------------------------------------- combine (unrolled 64-split reduce)
template<int FINAL>
__global__ void __launch_bounds__(BLK) combine_kernel(
        const float* __restrict__ emis, const float* __restrict__ brdf,
        int N, float* __restrict__ out) {
    int idx = blockIdx.x * BLK + threadIdx.x;   // 0 .. 3N-1
    float g = 0.f;
    #pragma unroll
    for (int s = 0; s < JS2; s++)
        g += g_part[(size_t)s * NMAX * 3 + idx];
    bool light = (idx >= 3 * (N - NLIGHTS));
    float e = emis[idx];
    float b = light ? e : fmaf(brdf[idx], g, e);
    if (FINAL) out[idx] = fmaxf(b, 0.f);
    else       g_B[idx] = b;
}

// ------------------------- bounce 3: matvec (plateau shape, 512 blocks)
__global__ void __launch_bounds__(MBLK) matvec_kernel(int N) {
    __shared__ float4 sB[JT3];
    int tid = threadIdx.x;
    int j0 = blockIdx.y * JT3;
    if (tid < JT3) {
        int jg = j0 + tid;
        sB[tid] = make_float4(g_B[3*jg] * INV_S, g_B[3*jg+1] * INV_S,
                              g_B[3*jg+2] * INV_S, 0.f);
    }
    __syncthreads();

    int i0 = (blockIdx.x * MBLK + tid) * IT3;
    float c00=0.f,c01=0.f,c02=0.f, c10=0.f,c11=0.f,c12=0.f;
    float c20=0.f,c21=0.f,c22=0.f, c30=0.f,c31=0.f,c32=0.f;

    const __half* fp = g_F + (size_t)j0 * N + i0;
    #pragma unroll
    for (int jo = 0; jo < JT3; jo += 16) {
        uint2 w[16];
        #pragma unroll
        for (int u = 0; u < 16; u++)
            w[u] = *(const uint2*)(fp + (size_t)(jo + u) * N);
        #pragma unroll
        for (int u = 0; u < 16; u++) {
            float4 b = sB[jo + u];
            float2 f0 = __half22float2(*(const __half2*)&w[u].x);
            float2 f1 = __half22float2(*(const __half2*)&w[u].y);
            c00 = fmaf(f0.x, b.x, c00); c01 = fmaf(f0.x, b.y, c01); c02 = fmaf(f0.x, b.z, c02);
            c10 = fmaf(f0.y, b.x, c10); c11 = fmaf(f0.y, b.y, c11); c12 = fmaf(f0.y, b.z, c12);
            c20 = fmaf(f1.x, b.x, c20); c21 = fmaf(f1.x, b.y, c21); c22 = fmaf(f1.x, b.z, c22);
            c30 = fmaf(f1.y, b.x, c30); c31 = fmaf(f1.y, b.y, c31); c32 = fmaf(f1.y, b.z, c32);
        }
    }

    float* p = g_part + (size_t)blockIdx.y * NMAX * 3 + 3 * i0;
    ((float4*)p)[0] = make_float4(c00, c01, c02, c10);
    ((float4*)p)[1] = make_float4(c11, c12, c20, c21);
    ((float4*)p)[2] = make_float4(c22, c30, c31, c32);
}

extern "C" void kernel_launch(void* const* d_in, const int* in_sizes, int n_in,
                              void* d_out, int out_size) {
    const float* means   = (const float*)d_in[0];
    const float* geo     = (const float*)d_in[1];
    const float* scales  = (const float*)d_in[2];
    // d_in[3] = rots — unused (API parity only, per reference)
    const float* normals = (const float*)d_in[4];
    const float* nf      = (const float*)d_in[5];
    const float* emis    = (const float*)d_in[6];
    const float* brdf    = (const float*)d_in[7];
    float* out = (float*)d_out;

    int N = in_sizes[1];              // 4096
    int nIB = (N + BLK - 1) / BLK;    // 16

    // Bounce 1 (sparse over tail lights, combine fused) -> g_B
    bounce1_kernel<<<nIB, BLK>>>(means, geo, scales, normals, nf, emis, brdf, N);

    // Bounce 2: bilinear build of F_T + gather, then unrolled combine -> g_B
    build_kernel<<<dim3(N / (PBLK * 4), JS2), PBLK>>>(means, geo, scales, normals, nf, N);
    combine_kernel<0><<<(N * 3) / BLK, BLK>>>(emis, brdf, N, out);

    // Bounce 3: matvec over F_T + final combine (relu) -> d_out
    matvec_kernel<<<dim3(N / (MBLK * IT3), JS3), MBLK>>>(N);
    combine_kernel<1><<<(N * 3) / BLK, BLK>>>(emis, brdf, N, out);
}